// round 5
// baseline (speedup 1.0000x reference)
#include <cuda_runtime.h>
#include <cuda_bf16.h>
#include <cstdint>

// ============================================================================
// out[b,c] = xs[b] + ps[c] - 2 * dot(x_b, p_c)
//   x = 3*l2norm(inputs) [4096,128], p = 3*l2norm(kernel) [16384,128]
// Legacy mma.sync.m16n8k16 bf16 (tcgen05 unavailable on plain sm_103 target).
// R5: persistent CTAs (296 = one wave @ 2/SM), each works a contiguous chunk
//     of n-major 128x128 tiles; B double-buffered via cp.async prefetch so
//     tile-load latency is hidden; A reloaded only on m-row crossings.
// ============================================================================

static constexpr int B_ROWS = 4096;
static constexpr int C_ROWS = 16384;
static constexpr int D_DIM  = 128;

static constexpr int MT = 128;
static constexpr int NT = 128;
static constexpr int N_TILES  = C_ROWS / NT;          // 128
static constexpr int M_TILES  = B_ROWS / MT;          // 32
static constexpr int TOT_TILES = N_TILES * M_TILES;   // 4096

static constexpr int GRID = 296;                      // 2 CTAs/SM, one wave
static constexpr int CHUNK = (TOT_TILES + GRID - 1) / GRID;  // 14

static constexpr int SMEM_A_OFF  = 0;
static constexpr int TILE_BYTES  = 128 * 256;         // 32768
static constexpr int SMEM_B0_OFF = TILE_BYTES;        // 32768
static constexpr int SMEM_B1_OFF = 2 * TILE_BYTES;    // 65536
static constexpr int SMEM_TOTAL  = 3 * TILE_BYTES;    // 98304

// ---------------- scratch (no allocation allowed) ----------------
__device__ __nv_bfloat16 g_x[B_ROWS * D_DIM];
__device__ __nv_bfloat16 g_p[C_ROWS * D_DIM];
__device__ float g_xs[B_ROWS];
__device__ float g_ps[C_ROWS];

__device__ __forceinline__ uint32_t smem_u32(const void* p) {
    uint32_t a;
    asm("{ .reg .u64 t; cvta.to.shared.u64 t, %1; cvt.u32.u64 %0, t; }" : "=r"(a) : "l"(p));
    return a;
}
__device__ __forceinline__ void cp_async16(uint32_t dst, const void* src) {
    asm volatile("cp.async.cg.shared.global [%0], [%1], 16;" :: "r"(dst), "l"(src));
}
__device__ __forceinline__ void ldmatrix_x4(uint32_t& r0, uint32_t& r1,
                                            uint32_t& r2, uint32_t& r3, uint32_t addr) {
    asm volatile("ldmatrix.sync.aligned.m8n8.x4.shared.b16 {%0,%1,%2,%3}, [%4];"
                 : "=r"(r0), "=r"(r1), "=r"(r2), "=r"(r3) : "r"(addr));
}
__device__ __forceinline__ void mma_bf16(float& c0, float& c1, float& c2, float& c3,
                                         uint32_t a0, uint32_t a1, uint32_t a2, uint32_t a3,
                                         uint32_t b0, uint32_t b1) {
    asm volatile(
        "mma.sync.aligned.m16n8k16.row.col.f32.bf16.bf16.f32 "
        "{%0,%1,%2,%3}, {%4,%5,%6,%7}, {%8,%9}, {%0,%1,%2,%3};"
        : "+f"(c0), "+f"(c1), "+f"(c2), "+f"(c3)
        : "r"(a0), "r"(a1), "r"(a2), "r"(a3), "r"(b0), "r"(b1));
}

// ============================================================================
// Kernel 1: normalize ALL rows -> bf16 + per-row sum-of-squares
// ============================================================================
__global__ __launch_bounds__(256)
void normalize_kernel(const float* __restrict__ inp, const float* __restrict__ ker) {
    int warp = (blockIdx.x * blockDim.x + threadIdx.x) >> 5;
    int lane = threadIdx.x & 31;
    if (warp >= B_ROWS + C_ROWS) return;

    const float* src;
    __nv_bfloat16* outv;
    float* outs;
    int row;
    if (warp < B_ROWS) { src = inp; outv = g_x; outs = g_xs; row = warp; }
    else { src = ker; outv = g_p; outs = g_ps; row = warp - B_ROWS; }

    float4 v = reinterpret_cast<const float4*>(src + (size_t)row * D_DIM)[lane];
    float ss = v.x * v.x + v.y * v.y + v.z * v.z + v.w * v.w;
    #pragma unroll
    for (int o = 16; o; o >>= 1) ss += __shfl_xor_sync(0xffffffffu, ss, o);

    float r = rsqrtf(fmaxf(ss, 1e-12f));
    float s = 3.0f * r;
    __nv_bfloat162 h0 = __floats2bfloat162_rn(v.x * s, v.y * s);
    __nv_bfloat162 h1 = __floats2bfloat162_rn(v.z * s, v.w * s);
    uint2 pk;
    pk.x = *reinterpret_cast<uint32_t*>(&h0);
    pk.y = *reinterpret_cast<uint32_t*>(&h1);
    reinterpret_cast<uint2*>(outv + (size_t)row * D_DIM)[lane] = pk;

    if (lane == 0) outs[row] = 9.0f * ss * r * r;   // == sum(x*x)
}

// helper: async-load one 128x128 bf16 tile (row-major 256B rows) into swizzled smem
__device__ __forceinline__ void load_tile_async(uint32_t smem_dst, const __nv_bfloat16* gsrc,
                                                int tid) {
    const char* src = reinterpret_cast<const char*>(gsrc);
    #pragma unroll
    for (int it = 0; it < 16; it++) {
        int i = it * 128 + tid;              // 2048 chunks of 16B
        int row = i >> 4, c = i & 15;
        uint32_t doff = row * 256 + ((c ^ (row & 7)) << 4);
        cp_async16(smem_dst + doff, src + (size_t)row * 256 + c * 16);
    }
}

// ============================================================================
// Kernel 2: persistent bf16 mma.sync GEMM with B double-buffering.
// CTA 128x128, 4 warps @ 64x64. SMEM rows 256B, chunk c ^ (row&7) swizzle.
// ============================================================================
__global__ __launch_bounds__(128, 2)
void gemm_kernel(float* __restrict__ out) {
    extern __shared__ char smem[];
    const uint32_t sb = smem_u32(smem);

    const int tid  = threadIdx.x;
    const int lane = tid & 31;
    const int wid  = tid >> 5;
    const int warp_m = wid & 1;
    const int warp_n = wid >> 1;

    int g0 = blockIdx.x * CHUNK;
    int g1 = min(g0 + CHUNK, TOT_TILES);
    if (g0 >= g1) return;

    // n-major tile order: g -> (m_tile = g>>7, n_tile = g&127)
    int m_tile = g0 >> 7;

    // ---- prologue: A(m_tile) + B(first tile) -> buf0 ----
    load_tile_async(sb + SMEM_A_OFF, g_x + (size_t)(m_tile << 7) * D_DIM, tid);
    load_tile_async(sb + SMEM_B0_OFF, g_p + (size_t)((g0 & 127) << 7) * D_DIM, tid);
    asm volatile("cp.async.commit_group;");

    const int a_row_base = warp_m * 64 + (lane & 7) + ((lane >> 3) & 1) * 8;
    const int a_kc_lane  = (lane >> 4);
    const int b_row_base = warp_n * 64 + (lane & 7) + (lane >> 4) * 8;
    const int b_kc_lane  = ((lane >> 3) & 1);

    int cur = 0;
    for (int g = g0; g < g1; g++) {
        asm volatile("cp.async.wait_group 0;" ::: "memory");
        __syncthreads();

        const bool has_next = (g + 1 < g1);
        const int  next_m   = (g + 1) >> 7;

        // prefetch next B while we compute on current
        if (has_next) {
            load_tile_async(sb + (cur ? SMEM_B0_OFF : SMEM_B1_OFF),
                            g_p + (size_t)(((g + 1) & 127) << 7) * D_DIM, tid);
            asm volatile("cp.async.commit_group;");
        }

        // ---- compute 128x128 tile ----
        float acc[4][8][4];
        #pragma unroll
        for (int mi = 0; mi < 4; mi++)
            #pragma unroll
            for (int ni = 0; ni < 8; ni++)
                #pragma unroll
                for (int k = 0; k < 4; k++) acc[mi][ni][k] = 0.0f;

        const uint32_t sbB = sb + (cur ? SMEM_B1_OFF : SMEM_B0_OFF);

        #pragma unroll
        for (int ks = 0; ks < 8; ks++) {
            uint32_t a[4][4];
            #pragma unroll
            for (int mi = 0; mi < 4; mi++) {
                int row = a_row_base + mi * 16;
                int kc  = ks * 2 + a_kc_lane;
                uint32_t addr = sb + SMEM_A_OFF + row * 256 + ((kc ^ (row & 7)) << 4);
                ldmatrix_x4(a[mi][0], a[mi][1], a[mi][2], a[mi][3], addr);
            }
            uint32_t b[8][2];
            #pragma unroll
            for (int gg = 0; gg < 4; gg++) {
                int row = b_row_base + gg * 16;
                int kc  = ks * 2 + b_kc_lane;
                uint32_t addr = sbB + row * 256 + ((kc ^ (row & 7)) << 4);
                ldmatrix_x4(b[2 * gg][0], b[2 * gg][1], b[2 * gg + 1][0], b[2 * gg + 1][1], addr);
            }
            #pragma unroll
            for (int mi = 0; mi < 4; mi++)
                #pragma unroll
                for (int ni = 0; ni < 8; ni++)
                    mma_bf16(acc[mi][ni][0], acc[mi][ni][1], acc[mi][ni][2], acc[mi][ni][3],
                             a[mi][0], a[mi][1], a[mi][2], a[mi][3],
                             b[ni][0], b[ni][1]);
        }

        // ---- epilogue: out = xs[m] + ps[n] - 2*acc ----
        {
            const int n0 = (g & 127) << 7;
            const int m0 = (g >> 7) << 7;
            const int c_base = n0 + warp_n * 64 + (lane & 3) * 2;
            float2 ps[8];
            #pragma unroll
            for (int ni = 0; ni < 8; ni++)
                ps[ni] = *reinterpret_cast<const float2*>(g_ps + c_base + ni * 8);

            #pragma unroll
            for (int mi = 0; mi < 4; mi++) {
                int r0 = m0 + warp_m * 64 + mi * 16 + (lane >> 2);
                float xs0 = g_xs[r0];
                float xs1 = g_xs[r0 + 8];
                float* o0 = out + (size_t)r0 * C_ROWS + c_base;
                float* o1 = out + (size_t)(r0 + 8) * C_ROWS + c_base;
                #pragma unroll
                for (int ni = 0; ni < 8; ni++) {
                    float2 v0, v1;
                    v0.x = xs0 + ps[ni].x - 2.0f * acc[mi][ni][0];
                    v0.y = xs0 + ps[ni].y - 2.0f * acc[mi][ni][1];
                    v1.x = xs1 + ps[ni].x - 2.0f * acc[mi][ni][2];
                    v1.y = xs1 + ps[ni].y - 2.0f * acc[mi][ni][3];
                    *reinterpret_cast<float2*>(o0 + ni * 8) = v0;
                    *reinterpret_cast<float2*>(o1 + ni * 8) = v1;
                }
            }
        }

        // ---- A reload on m-row crossing (rare: <=1 per CTA) ----
        if (has_next && next_m != (g >> 7)) {
            __syncthreads();   // all warps done reading A
            load_tile_async(sb + SMEM_A_OFF, g_x + (size_t)(next_m << 7) * D_DIM, tid);
            asm volatile("cp.async.commit_group;");
        }

        cur ^= 1;
    }
}

// ============================================================================
extern "C" void kernel_launch(void* const* d_in, const int* in_sizes, int n_in,
                              void* d_out, int out_size) {
    (void)in_sizes; (void)n_in; (void)out_size;
    const float* inp = (const float*)d_in[0];   // inputs [4096,128] fp32
    const float* ker = (const float*)d_in[1];   // kernel [16384,128] fp32
    float* out = (float*)d_out;                 // [4096,16384] fp32

    cudaFuncSetAttribute(gemm_kernel, cudaFuncAttributeMaxDynamicSharedMemorySize, SMEM_TOTAL);

    int total_warps = B_ROWS + C_ROWS;
    normalize_kernel<<<(total_warps * 32 + 255) / 256, 256>>>(inp, ker);

    gemm_kernel<<<GRID, 128, SMEM_TOTAL>>>(out);
}

// round 6
// speedup vs baseline: 1.0615x; 1.0615x over previous
#include <cuda_runtime.h>
#include <cuda_bf16.h>
#include <cstdint>

// ============================================================================
// out[b,c] = xs[b] + ps[c] - 2 * dot(x_b, p_c)
//   x = 3*l2norm(inputs) [4096,128], p = 3*l2norm(kernel) [16384,128]
// Legacy mma.sync.m16n8k16 bf16 (tcgen05 unavailable on plain sm_103 target).
// R6: coalesced epilogue via SMEM staging in the dead B buffer (full-line
//     st.global.cs.v4 stores), balanced persistent chunks, faster normalize.
// ============================================================================

static constexpr int B_ROWS = 4096;
static constexpr int C_ROWS = 16384;
static constexpr int D_DIM  = 128;

static constexpr int N_TILES   = C_ROWS / 128;        // 128
static constexpr int M_TILES   = B_ROWS / 128;        // 32
static constexpr int TOT_TILES = N_TILES * M_TILES;   // 4096

static constexpr int GRID = 296;                      // 2 CTAs/SM, one wave
static constexpr int BASE_CHUNK = TOT_TILES / GRID;   // 13
static constexpr int REM_CHUNK  = TOT_TILES % GRID;   // 248

static constexpr int SMEM_A_OFF  = 0;
static constexpr int TILE_BYTES  = 128 * 256;         // 32768
static constexpr int SMEM_B0_OFF = TILE_BYTES;
static constexpr int SMEM_B1_OFF = 2 * TILE_BYTES;
static constexpr int SMEM_TOTAL  = 3 * TILE_BYTES;    // 98304

// ---------------- scratch (no allocation allowed) ----------------
__device__ __nv_bfloat16 g_x[B_ROWS * D_DIM];
__device__ __nv_bfloat16 g_p[C_ROWS * D_DIM];
__device__ float g_xs[B_ROWS];
__device__ float g_ps[C_ROWS];

__device__ __forceinline__ uint32_t smem_u32(const void* p) {
    uint32_t a;
    asm("{ .reg .u64 t; cvta.to.shared.u64 t, %1; cvt.u32.u64 %0, t; }" : "=r"(a) : "l"(p));
    return a;
}
__device__ __forceinline__ void cp_async16(uint32_t dst, const void* src) {
    asm volatile("cp.async.cg.shared.global [%0], [%1], 16;" :: "r"(dst), "l"(src));
}
__device__ __forceinline__ void ldmatrix_x4(uint32_t& r0, uint32_t& r1,
                                            uint32_t& r2, uint32_t& r3, uint32_t addr) {
    asm volatile("ldmatrix.sync.aligned.m8n8.x4.shared.b16 {%0,%1,%2,%3}, [%4];"
                 : "=r"(r0), "=r"(r1), "=r"(r2), "=r"(r3) : "r"(addr));
}
__device__ __forceinline__ void mma_bf16(float& c0, float& c1, float& c2, float& c3,
                                         uint32_t a0, uint32_t a1, uint32_t a2, uint32_t a3,
                                         uint32_t b0, uint32_t b1) {
    asm volatile(
        "mma.sync.aligned.m16n8k16.row.col.f32.bf16.bf16.f32 "
        "{%0,%1,%2,%3}, {%4,%5,%6,%7}, {%8,%9}, {%0,%1,%2,%3};"
        : "+f"(c0), "+f"(c1), "+f"(c2), "+f"(c3)
        : "r"(a0), "r"(a1), "r"(a2), "r"(a3), "r"(b0), "r"(b1));
}
__device__ __forceinline__ void sts_v2(uint32_t addr, float x, float y) {
    asm volatile("st.shared.v2.f32 [%0], {%1,%2};" :: "r"(addr), "f"(x), "f"(y));
}
__device__ __forceinline__ void lds_v4(uint32_t addr, float& x, float& y, float& z, float& w) {
    asm volatile("ld.shared.v4.f32 {%0,%1,%2,%3}, [%4];"
                 : "=f"(x), "=f"(y), "=f"(z), "=f"(w) : "r"(addr));
}
__device__ __forceinline__ void stg_cs_v4(float* p, float x, float y, float z, float w) {
    asm volatile("st.global.cs.v4.f32 [%0], {%1,%2,%3,%4};"
                 :: "l"(p), "f"(x), "f"(y), "f"(z), "f"(w) : "memory");
}

// ============================================================================
// Kernel 1: normalize, 2 rows per warp (16 lanes/row) for 2x MLP
// ============================================================================
__global__ __launch_bounds__(256)
void normalize_kernel(const float* __restrict__ inp, const float* __restrict__ ker) {
    int warp = (blockIdx.x * blockDim.x + threadIdx.x) >> 5;
    int lane = threadIdx.x & 31;
    int row = warp * 2 + (lane >> 4);
    if (row >= B_ROWS + C_ROWS) return;

    const float* src;
    __nv_bfloat16* outv;
    float* outs;
    int r;
    if (row < B_ROWS) { src = inp; outv = g_x; outs = g_xs; r = row; }
    else { src = ker; outv = g_p; outs = g_ps; r = row - B_ROWS; }

    int j = lane & 15;
    const float4* s4 = reinterpret_cast<const float4*>(src + (size_t)r * D_DIM);
    float4 u = s4[j * 2];
    float4 w = s4[j * 2 + 1];
    float ss = u.x * u.x + u.y * u.y + u.z * u.z + u.w * u.w
             + w.x * w.x + w.y * w.y + w.z * w.z + w.w * w.w;
    #pragma unroll
    for (int o = 8; o; o >>= 1) ss += __shfl_xor_sync(0xffffffffu, ss, o);

    float rs = rsqrtf(fmaxf(ss, 1e-12f));
    float s = 3.0f * rs;
    __nv_bfloat162 h0 = __floats2bfloat162_rn(u.x * s, u.y * s);
    __nv_bfloat162 h1 = __floats2bfloat162_rn(u.z * s, u.w * s);
    __nv_bfloat162 h2 = __floats2bfloat162_rn(w.x * s, w.y * s);
    __nv_bfloat162 h3 = __floats2bfloat162_rn(w.z * s, w.w * s);
    uint4 pk;
    pk.x = *reinterpret_cast<uint32_t*>(&h0);
    pk.y = *reinterpret_cast<uint32_t*>(&h1);
    pk.z = *reinterpret_cast<uint32_t*>(&h2);
    pk.w = *reinterpret_cast<uint32_t*>(&h3);
    reinterpret_cast<uint4*>(outv + (size_t)r * D_DIM)[j] = pk;

    if (j == 0) outs[r] = 9.0f * ss * rs * rs;
}

// async-load one 128x128 bf16 tile (row-major 256B rows) into swizzled smem
__device__ __forceinline__ void load_tile_async(uint32_t smem_dst, const __nv_bfloat16* gsrc,
                                                int tid) {
    const char* src = reinterpret_cast<const char*>(gsrc);
    #pragma unroll
    for (int it = 0; it < 16; it++) {
        int i = it * 128 + tid;
        int row = i >> 4, c = i & 15;
        uint32_t doff = row * 256 + ((c ^ (row & 7)) << 4);
        cp_async16(smem_dst + doff, src + (size_t)row * 256 + c * 16);
    }
}

// ============================================================================
// Kernel 2: persistent bf16 mma.sync GEMM, B double-buffered, staged epilogue.
// ============================================================================
__global__ __launch_bounds__(128, 2)
void gemm_kernel(float* __restrict__ out) {
    extern __shared__ char smem[];
    const uint32_t sb = smem_u32(smem);

    const int tid  = threadIdx.x;
    const int lane = tid & 31;
    const int wid  = tid >> 5;
    const int warp_m = wid & 1;
    const int warp_n = wid >> 1;

    const int bid = blockIdx.x;
    int g0 = bid * BASE_CHUNK + min(bid, REM_CHUNK);
    int g1 = g0 + BASE_CHUNK + (bid < REM_CHUNK ? 1 : 0);

    // n-major tile order: g -> (m_tile = g>>7, n_tile = g&127)
    load_tile_async(sb + SMEM_A_OFF, g_x + (size_t)((g0 >> 7) << 7) * D_DIM, tid);
    load_tile_async(sb + SMEM_B0_OFF, g_p + (size_t)((g0 & 127) << 7) * D_DIM, tid);
    asm volatile("cp.async.commit_group;");

    const int a_row_base = warp_m * 64 + (lane & 7) + ((lane >> 3) & 1) * 8;
    const int a_kc_lane  = (lane >> 4);
    const int b_row_base = warp_n * 64 + (lane & 7) + (lane >> 4) * 8;
    const int b_kc_lane  = ((lane >> 3) & 1);

    int cur = 0;
    for (int g = g0; g < g1; g++) {
        asm volatile("cp.async.wait_group 0;" ::: "memory");
        __syncthreads();

        const bool has_next = (g + 1 < g1);
        const int  next_m   = (g + 1) >> 7;

        if (has_next) {
            load_tile_async(sb + (cur ? SMEM_B0_OFF : SMEM_B1_OFF),
                            g_p + (size_t)(((g + 1) & 127) << 7) * D_DIM, tid);
            asm volatile("cp.async.commit_group;");
        }

        // ---- compute 128x128 tile ----
        float acc[4][8][4];
        #pragma unroll
        for (int mi = 0; mi < 4; mi++)
            #pragma unroll
            for (int ni = 0; ni < 8; ni++)
                #pragma unroll
                for (int k = 0; k < 4; k++) acc[mi][ni][k] = 0.0f;

        const uint32_t sbB = sb + (cur ? SMEM_B1_OFF : SMEM_B0_OFF);

        #pragma unroll
        for (int ks = 0; ks < 8; ks++) {
            uint32_t a[4][4];
            #pragma unroll
            for (int mi = 0; mi < 4; mi++) {
                int row = a_row_base + mi * 16;
                int kc  = ks * 2 + a_kc_lane;
                uint32_t addr = sb + SMEM_A_OFF + row * 256 + ((kc ^ (row & 7)) << 4);
                ldmatrix_x4(a[mi][0], a[mi][1], a[mi][2], a[mi][3], addr);
            }
            uint32_t b[8][2];
            #pragma unroll
            for (int gg = 0; gg < 4; gg++) {
                int row = b_row_base + gg * 16;
                int kc  = ks * 2 + b_kc_lane;
                uint32_t addr = sbB + row * 256 + ((kc ^ (row & 7)) << 4);
                ldmatrix_x4(b[2 * gg][0], b[2 * gg][1], b[2 * gg + 1][0], b[2 * gg + 1][1], addr);
            }
            #pragma unroll
            for (int mi = 0; mi < 4; mi++)
                #pragma unroll
                for (int ni = 0; ni < 8; ni++)
                    mma_bf16(acc[mi][ni][0], acc[mi][ni][1], acc[mi][ni][2], acc[mi][ni][3],
                             a[mi][0], a[mi][1], a[mi][2], a[mi][3],
                             b[ni][0], b[ni][1]);
        }

        // all warps done reading B before we reuse it as staging
        __syncthreads();

        // ---- staged epilogue: out = xs[m] + ps[n] - 2*acc, full-line stores ----
        {
            const int n0 = (g & 127) << 7;
            const int m0 = (g >> 7) << 7;
            const int c_col0 = n0 + warp_n * 64;
            const int c_base = c_col0 + (lane & 3) * 2;
            float2 ps[8];
            #pragma unroll
            for (int ni = 0; ni < 8; ni++)
                ps[ni] = *reinterpret_cast<const float2*>(g_ps + c_base + ni * 8);

            const uint32_t stg = sbB + wid * 4096;   // dead B buffer, 4KB/warp
            const int row0 = lane >> 2;              // 0..7
            const int ib   = (lane & 3) << 3;

            #pragma unroll
            for (int mi = 0; mi < 4; mi++) {
                int r_base = m0 + warp_m * 64 + mi * 16;
                float xs0 = g_xs[r_base + row0];
                float xs1 = g_xs[r_base + 8 + row0];

                #pragma unroll
                for (int ni = 0; ni < 8; ni++) {
                    uint32_t chunk = (uint32_t)(ni ^ row0) << 5;
                    sts_v2(stg + row0 * 256 + chunk + ib,
                           xs0 + ps[ni].x - 2.0f * acc[mi][ni][0],
                           xs0 + ps[ni].y - 2.0f * acc[mi][ni][1]);
                    sts_v2(stg + (row0 + 8) * 256 + chunk + ib,
                           xs1 + ps[ni].x - 2.0f * acc[mi][ni][2],
                           xs1 + ps[ni].y - 2.0f * acc[mi][ni][3]);
                }
                __syncwarp();

                #pragma unroll
                for (int i = 0; i < 8; i++) {
                    int pos = i * 512 + lane * 16;
                    int rl  = pos >> 8;              // 0..15
                    int bib = pos & 255;
                    int ch  = bib >> 5;
                    uint32_t sa = stg + rl * 256 + ((uint32_t)(ch ^ (rl & 7)) << 5) + (bib & 31);
                    float x, y, z, w;
                    lds_v4(sa, x, y, z, w);
                    float* gp = out + (size_t)(r_base + rl) * C_ROWS + c_col0 + (bib >> 2);
                    stg_cs_v4(gp, x, y, z, w);
                }
                __syncwarp();
            }
        }

        // ---- A reload on m-row crossing ----
        if (has_next && next_m != (g >> 7)) {
            __syncthreads();
            load_tile_async(sb + SMEM_A_OFF, g_x + (size_t)(next_m << 7) * D_DIM, tid);
            asm volatile("cp.async.commit_group;");
        }

        cur ^= 1;
    }
}

// ============================================================================
extern "C" void kernel_launch(void* const* d_in, const int* in_sizes, int n_in,
                              void* d_out, int out_size) {
    (void)in_sizes; (void)n_in; (void)out_size;
    const float* inp = (const float*)d_in[0];   // inputs [4096,128] fp32
    const float* ker = (const float*)d_in[1];   // kernel [16384,128] fp32
    float* out = (float*)d_out;                 // [4096,16384] fp32

    cudaFuncSetAttribute(gemm_kernel, cudaFuncAttributeMaxDynamicSharedMemorySize, SMEM_TOTAL);

    int total_rows = B_ROWS + C_ROWS;            // 2 rows per warp
    int nwarps = (total_rows + 1) / 2;
    normalize_kernel<<<(nwarps * 32 + 255) / 256, 256>>>(inp, ker);

    gemm_kernel<<<GRID, 128, SMEM_TOTAL>>>(out);
}